// round 5
// baseline (speedup 1.0000x reference)
#include <cuda_runtime.h>

#define Bq 8
#define Cq 64
#define CIq 32
#define Nq 2304          // 48*48
#define NP1 2305
#define TILES 36         // 2304/64
#define NTILE (Bq*TILES) // 288
#define NCH 72           // suffix-scan chunks per batch
#define CHSZ 32
#define GRIDB 288
#define NTHR 256

// ---------------- scratch (__device__ globals; no allocations) ----------------
__device__ float s_a[Bq*Nq];
__device__ float s_b[Bq*Nq];
__device__ float s_gx[Bq*Nq*CIq];          // [b][n][i]
__device__ float s_keys[Bq*Nq];            // sorted b ascending (stable)
__device__ int   s_perm[Bq*Nq];
__device__ int   s_kstar[Bq*Nq];
__device__ float s_ctg[Bq*NCH*CIq];        // chunk totals (g)
__device__ float s_ctbg[Bq*NCH*CIq];       // chunk totals (b*g)
__device__ float s_Sg[Bq*NP1*CIq];         // inclusive suffix sums
__device__ float s_Sbg[Bq*NP1*CIq];
__device__ float s_wy[Bq*Cq*Nq];           // pre-BN output
__device__ float s_part[NTILE*Cq*2];       // per-tile (sum, sumsq)

// grid barrier state
__device__ unsigned g_bar = 0;
__device__ volatile unsigned g_gen = 0;

__device__ __forceinline__ void gsync() {
    __syncthreads();
    if (threadIdx.x == 0) {
        __threadfence();
        unsigned gen = g_gen;
        if (atomicAdd(&g_bar, 1u) == gridDim.x - 1) {
            g_bar = 0;
            __threadfence();
            g_gen = gen + 1;
        } else {
            while (g_gen == gen) { __nanosleep(32); }
        }
        __threadfence();
    }
    __syncthreads();
}

__global__ __launch_bounds__(NTHR, 2) void fused_nonlocal(
    const float* __restrict__ x,
    const float* __restrict__ g_w,  const float* __restrict__ g_b,
    const float* __restrict__ th_w, const float* __restrict__ th_b,
    const float* __restrict__ ph_w, const float* __restrict__ ph_b,
    const float* __restrict__ cp_wt, const float* __restrict__ cp_wp,
    const float* __restrict__ W_w,  const float* __restrict__ W_b,
    const float* __restrict__ bn_g, const float* __restrict__ bn_b,
    float* __restrict__ out)
{
    __shared__ __align__(16) unsigned char SM[26624];
    int t = threadIdx.x;
    int w = t >> 5, lane = t & 31;

    // ================= P1: projections (gx, a, b); one tile per block ==========
    {
        float* xs  = (float*)SM;                      // 64*68 = 17408B
        float* gws = (float*)(SM + 17408);            // 32*65 = 8320B
        float* was = (float*)(SM + 25728);            // 64
        float* wbs = (float*)(SM + 25984);            // 64
        float* cst = (float*)(SM + 26240);            // 2
        float* gbs = (float*)(SM + 26256);            // 32

        int b = blockIdx.x / TILES, n0 = (blockIdx.x % TILES) * 64;

        if (t < 64) {
            float sa = 0.f, sb = 0.f;
            #pragma unroll
            for (int i = 0; i < CIq; i++) {
                sa = fmaf(cp_wt[i], th_w[i*Cq + t], sa);
                sb = fmaf(cp_wp[i], ph_w[i*Cq + t], sb);
            }
            was[t] = sa; wbs[t] = sb;
        } else if (t == 64) {
            float ca = 0.f;
            #pragma unroll
            for (int i = 0; i < CIq; i++) ca = fmaf(cp_wt[i], th_b[i], ca);
            cst[0] = ca;
        } else if (t == 65) {
            float cb = 0.f;
            #pragma unroll
            for (int i = 0; i < CIq; i++) cb = fmaf(cp_wp[i], ph_b[i], cb);
            cst[1] = cb;
        }
        if (t >= 128 && t < 160) gbs[t - 128] = g_b[t - 128];
        for (int idx = t; idx < CIq*Cq; idx += NTHR)
            gws[(idx >> 6)*65 + (idx & 63)] = g_w[idx];
        {
            float4* xs4 = (float4*)xs;
            const float4* xg = (const float4*)x;
            for (int idx = t; idx < Cq*16; idx += NTHR) {
                int c = idx >> 4, q = idx & 15;
                xs4[c*17 + q] = xg[(((b*Cq + c)*Nq + n0) >> 2) + q];
            }
        }
        __syncthreads();

        int i = t & 31, pg = t >> 5;
        float acc[8];
        float gb_i = gbs[i];
        #pragma unroll
        for (int p = 0; p < 8; p++) acc[p] = gb_i;
        #pragma unroll
        for (int c = 0; c < Cq; c++) {
            float ww = gws[i*65 + c];
            float4 xa = *(const float4*)&xs[c*68 + pg*8];
            float4 xb = *(const float4*)&xs[c*68 + pg*8 + 4];
            acc[0] = fmaf(ww, xa.x, acc[0]); acc[1] = fmaf(ww, xa.y, acc[1]);
            acc[2] = fmaf(ww, xa.z, acc[2]); acc[3] = fmaf(ww, xa.w, acc[3]);
            acc[4] = fmaf(ww, xb.x, acc[4]); acc[5] = fmaf(ww, xb.y, acc[5]);
            acc[6] = fmaf(ww, xb.z, acc[6]); acc[7] = fmaf(ww, xb.w, acc[7]);
        }
        #pragma unroll
        for (int p = 0; p < 8; p++)
            s_gx[(b*Nq + n0 + pg*8 + p)*CIq + i] = acc[p];

        if (t < 64) {
            float aa = cst[0], bb = cst[1];
            #pragma unroll
            for (int c = 0; c < Cq; c++) {
                float xv = xs[c*68 + t];
                aa = fmaf(was[c], xv, aa);
                bb = fmaf(wbs[c], xv, bb);
            }
            s_a[b*Nq + n0 + t] = aa;
            s_b[b*Nq + n0 + t] = bb;
        }
    }
    gsync();

    // ====== P2: stable rank + k* by counting (one 64-pos slice per block) ======
    {
        unsigned* osb  = (unsigned*)SM;               // 2304 = 9216B
        unsigned* cntR = (unsigned*)(SM + 9216);      // 4*64
        unsigned* cntK = (unsigned*)(SM + 10240);     // 4*64

        int b = blockIdx.x / 36, slice = blockIdx.x % 36;
        int pos_base = slice * 64;
        for (int idx = t; idx < Nq; idx += NTHR) {
            int iv = __float_as_int(s_b[b*Nq + idx]);
            osb[idx] = (unsigned)(iv ^ ((iv >> 31) | 0x80000000));
        }
        __syncthreads();

        int g = t & 63, s = t >> 6;                   // s: 0..3
        int m = pos_base + g;
        unsigned omR = osb[m];
        unsigned omK;
        {
            int iv = __float_as_int(-s_a[b*Nq + m]);
            omK = (unsigned)(iv ^ ((iv >> 31) | 0x80000000)) + 1u;
        }
        int jlo = s * 576, jhi = jlo + 576;
        unsigned cR = 0, cK = 0;
        const uint4* o4 = (const uint4*)osb;

        auto count_range = [&](int lo, int hi, unsigned thR) {
            for (int q = lo >> 2; q < (hi >> 2); q++) {
                uint4 v = o4[q];
                cR += (v.x < thR) + (v.y < thR) + (v.z < thR) + (v.w < thR);
                cK += (v.x < omK) + (v.y < omK) + (v.z < omK) + (v.w < omK);
            }
        };
        // split at m (ranges and m are 4-aligned-safe via scalar boundary)
        int A = min(max(m, jlo), jhi);
        // [jlo, A): threshold omR+1 (<=) ; [A, jhi): omR (<)
        {
            int Aa = A & ~3;
            count_range(jlo, Aa, omR + 1u);
            for (int j = Aa; j < A; j++) {
                unsigned v = osb[j]; cR += (v < omR + 1u); cK += (v < omK);
            }
            for (int j = A; j < ((A + 3) & ~3) && j < jhi; j++) {
                unsigned v = osb[j]; cR += (v < omR); cK += (v < omK);
            }
            int Ab = (A + 3) & ~3;
            if (Ab < jhi) count_range(Ab, jhi, omR);
        }

        cntR[s*64 + g] = cR;
        cntK[s*64 + g] = cK;
        __syncthreads();

        if (t < 64) {
            int pos = pos_base + t;
            unsigned rank = cntR[t] + cntR[64+t] + cntR[128+t] + cntR[192+t];
            unsigned kst  = cntK[t] + cntK[64+t] + cntK[128+t] + cntK[192+t];
            s_keys[b*Nq + rank] = s_b[b*Nq + pos];
            s_perm[b*Nq + rank] = pos;
            s_kstar[b*Nq + pos] = (int)kst;
        }
    }
    gsync();

    // ================= P3: chunk totals (one chunk per warp) ===================
    {
        int gwid = blockIdx.x * 8 + w;
        if (gwid < Bq*NCH) {
            int b = gwid / NCH, ch = gwid % NCH;
            int k0 = ch * CHSZ;
            int   mlane = s_perm[b*Nq + k0 + lane];
            float klane = s_keys[b*Nq + k0 + lane];
            const float* gxb = s_gx + b*Nq*CIq;
            float ag = 0.f, abg = 0.f;
            #pragma unroll
            for (int j = 0; j < 32; j++) {
                int   mm = __shfl_sync(0xffffffffu, mlane, j);
                float kk = __shfl_sync(0xffffffffu, klane, j);
                float gg = gxb[mm*CIq + lane];
                ag += gg;
                abg = fmaf(kk, gg, abg);
            }
            s_ctg [(b*NCH + ch)*CIq + lane] = ag;
            s_ctbg[(b*NCH + ch)*CIq + lane] = abg;
        }
    }
    gsync();

    // ============ P4: suffix-sum writes (half-chunk per warp) ==================
    {
        int u = blockIdx.x * 8 + w;
        if (u < Bq*NCH*2) {
            int cg = u >> 1, hc = u & 1;
            int b = cg / NCH, ch = cg % NCH;
            float rg = 0.f, rbg = 0.f;
            const float* ctg  = s_ctg  + b*NCH*CIq;
            const float* ctbg = s_ctbg + b*NCH*CIq;
            #pragma unroll 4
            for (int c2 = ch + 1; c2 < NCH; c2++) {
                rg  += ctg [c2*CIq + lane];
                rbg += ctbg[c2*CIq + lane];
            }
            int k0 = ch * CHSZ;
            int   mlane = s_perm[b*Nq + k0 + lane];
            float klane = s_keys[b*Nq + k0 + lane];
            const float* gxb = s_gx + b*Nq*CIq;
            if (hc == 0) {
                #pragma unroll
                for (int j = 31; j >= 16; j--) {
                    int   mm = __shfl_sync(0xffffffffu, mlane, j);
                    float kk = __shfl_sync(0xffffffffu, klane, j);
                    float gg = gxb[mm*CIq + lane];
                    rg += gg;
                    rbg = fmaf(kk, gg, rbg);
                }
            }
            int jstart = hc ? 16 : 0;
            float ag = rg, abg = rbg;
            #pragma unroll
            for (int j = jstart + 15; j >= jstart; j--) {
                int   mm = __shfl_sync(0xffffffffu, mlane, j);
                float kk = __shfl_sync(0xffffffffu, klane, j);
                float gg = gxb[mm*CIq + lane];
                ag += gg;
                abg = fmaf(kk, gg, abg);
                s_Sg [(b*NP1 + k0 + j)*CIq + lane] = ag;
                s_Sbg[(b*NP1 + k0 + j)*CIq + lane] = abg;
            }
        }
        if (blockIdx.x == 0) {      // empty-suffix rows, warps 0..7 = batches
            s_Sg [(w*NP1 + Nq)*CIq + lane] = 0.f;
            s_Sbg[(w*NP1 + Nq)*CIq + lane] = 0.f;
        }
    }
    gsync();

    // ============ P5: y lookup + W projection + BN partials (1 tile/block) =====
    {
        float* ws   = (float*)SM;                     // 64*33 = 8448B
        float* ys   = (float*)(SM + 8448);            // 64*36 = 9216B
        float* a_sm = (float*)(SM + 17664);           // 64
        int*   k_sm = (int*)(SM + 17920);             // 64
        float* psum = (float*)(SM + 18176);           // 4*64
        float* psq  = (float*)(SM + 19200);           // 4*64

        int b = blockIdx.x / TILES, n0 = (blockIdx.x % TILES) * 64;

        for (int idx = t; idx < Cq*CIq; idx += NTHR)
            ws[(idx >> 5)*33 + (idx & 31)] = W_w[idx];
        if (t < 64) {
            a_sm[t] = s_a[b*Nq + n0 + t];
            k_sm[t] = s_kstar[b*Nq + n0 + t];
        }
        __syncthreads();

        {
            int i = t & 31, pg = t >> 5;
            #pragma unroll
            for (int p = 0; p < 8; p++) {
                int pos = pg*8 + p;
                int k = k_sm[pos];
                float sg  = s_Sg [(b*NP1 + k)*CIq + i];
                float sbg = s_Sbg[(b*NP1 + k)*CIq + i];
                ys[pos*36 + i] = fmaf(a_sm[pos], sg, sbg) * (1.0f / (float)Nq);
            }
        }
        __syncthreads();

        {
            int c = t & 63, sub = t >> 6;
            float wreg[CIq];
            #pragma unroll
            for (int i = 0; i < CIq; i++) wreg[i] = ws[c*33 + i];
            float wbc = W_b[c];
            float ls = 0.f, ls2 = 0.f;
            float* wyrow = s_wy + (b*Cq + c)*Nq + n0 + sub*16;
            #pragma unroll
            for (int q4 = 0; q4 < 4; q4++) {
                float av[4];
                #pragma unroll
                for (int u = 0; u < 4; u++) {
                    int pos = sub*16 + q4*4 + u;
                    const float4* yv = (const float4*)&ys[pos*36];
                    float acc = 0.f;
                    #pragma unroll
                    for (int i4 = 0; i4 < CIq/4; i4++) {
                        float4 v = yv[i4];
                        acc = fmaf(wreg[i4*4+0], v.x, acc);
                        acc = fmaf(wreg[i4*4+1], v.y, acc);
                        acc = fmaf(wreg[i4*4+2], v.z, acc);
                        acc = fmaf(wreg[i4*4+3], v.w, acc);
                    }
                    av[u] = acc;
                    ls += acc; ls2 = fmaf(acc, acc, ls2);
                }
                float4 o;
                o.x = av[0] + wbc; o.y = av[1] + wbc;
                o.z = av[2] + wbc; o.w = av[3] + wbc;
                *(float4*)(wyrow + q4*4) = o;
            }
            psum[sub*64 + c] = ls;
            psq [sub*64 + c] = ls2;
        }
        __syncthreads();

        if (t < 64) {
            float s  = psum[t] + psum[64+t] + psum[128+t] + psum[192+t];
            float s2 = psq[t]  + psq[64+t]  + psq[128+t]  + psq[192+t];
            s_part[(blockIdx.x*Cq + t)*2 + 0] = s;
            s_part[(blockIdx.x*Cq + t)*2 + 1] = s2;
        }
    }
    gsync();

    // ================= P6: BN stats (redundant per block) + final ==============
    {
        float* red   = (float*)SM;            // [4][64]*2
        float* scale = (float*)(SM + 2048);   // 64
        float* shift = (float*)(SM + 2304);   // 64

        int c = t & 63, r = t >> 6;           // r: 0..3
        float s = 0.f, s2 = 0.f;
        const float2* pp = (const float2*)s_part;
        for (int blk = r; blk < NTILE; blk += 4) {
            float2 v = pp[blk*Cq + c];
            s += v.x; s2 += v.y;
        }
        red[r*64 + c] = s;
        red[256 + r*64 + c] = s2;
        __syncthreads();
        if (t < 64) {
            float ss = red[t] + red[64+t] + red[128+t] + red[192+t];
            float qq = red[256+t] + red[320+t] + red[384+t] + red[448+t];
            const float M = (float)(Bq * Nq);
            float mv = ss / M;
            float var = qq / M - mv*mv;
            float mean = W_b[t] + mv;
            float sc = bn_g[t] * rsqrtf(var + 1e-5f);
            scale[t] = sc;
            shift[t] = bn_b[t] - mean*sc;
        }
        __syncthreads();

        const int TOT4 = Bq*Cq*Nq/4;
        const float4* wy4 = (const float4*)s_wy;
        const float4* x4  = (const float4*)x;
        float4* o4 = (float4*)out;
        for (int i4 = blockIdx.x*NTHR + t; i4 < TOT4; i4 += GRIDB*NTHR) {
            int c2 = (i4 / (Nq/4)) & 63;
            float sc = scale[c2], sh = shift[c2];
            float4 ww = wy4[i4];
            float4 xv = x4[i4];
            float4 o;
            o.x = fmaf(ww.x, sc, sh) + xv.x;
            o.y = fmaf(ww.y, sc, sh) + xv.y;
            o.z = fmaf(ww.z, sc, sh) + xv.z;
            o.w = fmaf(ww.w, sc, sh) + xv.w;
            o4[i4] = o;
        }
    }
}

// ---------------- launch ----------------
extern "C" void kernel_launch(void* const* d_in, const int* in_sizes, int n_in,
                              void* d_out, int out_size) {
    const float* x     = (const float*)d_in[0];
    const float* g_w   = (const float*)d_in[1];
    const float* g_b   = (const float*)d_in[2];
    const float* th_w  = (const float*)d_in[3];
    const float* th_b  = (const float*)d_in[4];
    const float* ph_w  = (const float*)d_in[5];
    const float* ph_b  = (const float*)d_in[6];
    const float* cp_wt = (const float*)d_in[7];
    const float* cp_wp = (const float*)d_in[8];
    const float* W_w   = (const float*)d_in[9];
    const float* W_b   = (const float*)d_in[10];
    const float* bn_g  = (const float*)d_in[11];
    const float* bn_b  = (const float*)d_in[12];
    float* out = (float*)d_out;

    fused_nonlocal<<<GRIDB, NTHR>>>(x, g_w, g_b, th_w, th_b, ph_w, ph_b,
                                    cp_wt, cp_wp, W_w, W_b, bn_g, bn_b, out);
}

// round 6
// speedup vs baseline: 1.2443x; 1.2443x over previous
#include <cuda_runtime.h>

#define Bq 8
#define Cq 64
#define CIq 32
#define Nq 2304          // 48*48
#define NP1 2305
#define TILES 36         // 2304/64
#define NTILE (Bq*TILES) // 288
#define NCH 72           // suffix-scan chunks per batch
#define CHSZ 32
#define GRID 148
#define NTHR 512
#define NBUCK 2048

// ---------------- scratch (__device__ globals; no allocations) ----------------
__device__ float s_a[Bq*Nq];
__device__ float s_b[Bq*Nq];
__device__ float s_gx[Bq*Nq*CIq];          // [b][n][i]
__device__ float s_keys[Bq*Nq];            // sorted b ascending
__device__ int   s_perm[Bq*Nq];
__device__ int   s_kstar[Bq*Nq];
__device__ float s_ctg[Bq*NCH*CIq];        // chunk totals (g)
__device__ float s_ctbg[Bq*NCH*CIq];       // chunk totals (b*g)
__device__ float s_Sg[Bq*NP1*CIq];         // inclusive suffix sums
__device__ float s_Sbg[Bq*NP1*CIq];
__device__ float s_wy[Bq*Cq*Nq];           // pre-BN output
__device__ float s_part[NTILE*Cq*2];       // per-tile (sum, sumsq)

// grid barrier state
__device__ unsigned g_bar = 0;
__device__ volatile unsigned g_gen = 0;

__device__ __forceinline__ void gsync() {
    __syncthreads();
    if (threadIdx.x == 0) {
        __threadfence();
        unsigned gen = g_gen;
        if (atomicAdd(&g_bar, 1u) == gridDim.x - 1) {
            g_bar = 0;
            __threadfence();
            g_gen = gen + 1;
        } else {
            while (g_gen == gen) { __nanosleep(32); }
        }
        __threadfence();
    }
    __syncthreads();
}

__global__ __launch_bounds__(NTHR, 1) void fused_nonlocal(
    const float* __restrict__ x,
    const float* __restrict__ g_w,  const float* __restrict__ g_b,
    const float* __restrict__ th_w, const float* __restrict__ th_b,
    const float* __restrict__ ph_w, const float* __restrict__ ph_b,
    const float* __restrict__ cp_wt, const float* __restrict__ cp_wp,
    const float* __restrict__ W_w,  const float* __restrict__ W_b,
    const float* __restrict__ bn_g, const float* __restrict__ bn_b,
    float* __restrict__ out)
{
    __shared__ __align__(16) unsigned char SM[43808];
    int t = threadIdx.x;

    // ================= P1: projections (gx, a, b) =================
    {
        float* xs  = (float*)SM;                      // [2][64*68]
        float* gws = (float*)(SM + 34816);            // 32*65
        float* was = (float*)(SM + 43136);            // 64
        float* wbs = (float*)(SM + 43392);            // 64
        float* cst = (float*)(SM + 43648);            // 2
        float* gbs = (float*)(SM + 43664);            // 32

        if (t < 64) {
            float sa = 0.f, sb = 0.f;
            #pragma unroll
            for (int i = 0; i < CIq; i++) {
                sa = fmaf(cp_wt[i], th_w[i*Cq + t], sa);
                sb = fmaf(cp_wp[i], ph_w[i*Cq + t], sb);
            }
            was[t] = sa; wbs[t] = sb;
        } else if (t == 64) {
            float ca = 0.f;
            #pragma unroll
            for (int i = 0; i < CIq; i++) ca = fmaf(cp_wt[i], th_b[i], ca);
            cst[0] = ca;
        } else if (t == 65) {
            float cb = 0.f;
            #pragma unroll
            for (int i = 0; i < CIq; i++) cb = fmaf(cp_wp[i], ph_b[i], cb);
            cst[1] = cb;
        }
        if (t >= 128 && t < 160) gbs[t - 128] = g_b[t - 128];
        for (int idx = t; idx < CIq*Cq; idx += NTHR)
            gws[(idx >> 6)*65 + (idx & 63)] = g_w[idx];
        __syncthreads();

        int half = t >> 8, tt = t & 255;
        int i = tt & 31, pg = tt >> 5;
        float* xsh = xs + half*(64*68);
        float cst0 = cst[0], cst1 = cst[1];
        float gb_i = gbs[i];

        for (int pair = blockIdx.x; pair < NTILE/2; pair += GRID) {
            int tile = pair*2 + half;
            int b = tile / TILES, n0 = (tile % TILES)*64;
            float4* xs4 = (float4*)xsh;
            const float4* xg = (const float4*)x;
            for (int idx = tt; idx < Cq*16; idx += 256) {
                int c = idx >> 4, q = idx & 15;
                xs4[c*17 + q] = xg[(((b*Cq + c)*Nq + n0) >> 2) + q];
            }
            __syncthreads();

            float acc[8];
            #pragma unroll
            for (int p = 0; p < 8; p++) acc[p] = gb_i;
            #pragma unroll
            for (int c = 0; c < Cq; c++) {
                float w = gws[i*65 + c];
                float4 xa = *(const float4*)&xsh[c*68 + pg*8];
                float4 xb = *(const float4*)&xsh[c*68 + pg*8 + 4];
                acc[0] = fmaf(w, xa.x, acc[0]); acc[1] = fmaf(w, xa.y, acc[1]);
                acc[2] = fmaf(w, xa.z, acc[2]); acc[3] = fmaf(w, xa.w, acc[3]);
                acc[4] = fmaf(w, xb.x, acc[4]); acc[5] = fmaf(w, xb.y, acc[5]);
                acc[6] = fmaf(w, xb.z, acc[6]); acc[7] = fmaf(w, xb.w, acc[7]);
            }
            #pragma unroll
            for (int p = 0; p < 8; p++)
                s_gx[(b*Nq + n0 + pg*8 + p)*CIq + i] = acc[p];

            if (tt < 64) {
                float aa = cst0, bb = cst1;
                #pragma unroll
                for (int c = 0; c < Cq; c++) {
                    float xv = xsh[c*68 + tt];
                    aa = fmaf(was[c], xv, aa);
                    bb = fmaf(wbs[c], xv, bb);
                }
                s_a[b*Nq + n0 + tt] = aa;
                s_b[b*Nq + n0 + tt] = bb;
            }
            __syncthreads();
        }
    }
    gsync();

    // ===== P2: per-batch bucket sort (1 block per batch; ties need no order) ====
    if (blockIdx.x < Bq) {
        float* kb    = (float*)SM;                 // 2304 floats
        int*   blist = (int*)(SM + 9216);          // 2304 ints
        int*   off   = (int*)(SM + 18432);         // 2049 ints (hist -> offsets)
        int*   cnt   = (int*)(SM + 26640);         // 2048 ints
        int*   aux   = (int*)(SM + 34832);         // warp sums (16) + spare
        float* auxf  = (float*)(SM + 34912);       // 32 mins + 32 maxs + 2

        int b = blockIdx.x;
        int lane = t & 31, w = t >> 5;

        // zero hist; load keys with local min/max
        for (int idx = t; idx < NBUCK + 1; idx += NTHR) off[idx] = 0;
        float lmin = 3.4e38f, lmax = -3.4e38f;
        for (int m = t; m < Nq; m += NTHR) {
            float v = s_b[b*Nq + m];
            kb[m] = v;
            lmin = fminf(lmin, v); lmax = fmaxf(lmax, v);
        }
        #pragma unroll
        for (int d = 16; d > 0; d >>= 1) {
            lmin = fminf(lmin, __shfl_xor_sync(0xffffffffu, lmin, d));
            lmax = fmaxf(lmax, __shfl_xor_sync(0xffffffffu, lmax, d));
        }
        if (lane == 0) { auxf[w] = lmin; auxf[16 + w] = lmax; }
        __syncthreads();
        if (t == 0) {
            float mn = auxf[0], mx = auxf[16];
            for (int k = 1; k < 16; k++) {
                mn = fminf(mn, auxf[k]); mx = fmaxf(mx, auxf[16 + k]);
            }
            auxf[32] = mn;
            auxf[33] = (mx > mn) ? ((float)(NBUCK - 1) / (mx - mn)) : 0.f;
        }
        __syncthreads();
        float minv = auxf[32], scale = auxf[33];

        // histogram
        for (int m = t; m < Nq; m += NTHR) {
            int bk = (int)((kb[m] - minv) * scale);
            bk = max(0, min(NBUCK - 1, bk));
            atomicAdd(&off[bk], 1);
        }
        __syncthreads();

        // exclusive scan of 2048 buckets (4 per thread)
        int base = t * 4;
        int h0 = off[base], h1 = off[base+1], h2 = off[base+2], h3 = off[base+3];
        int tsum = h0 + h1 + h2 + h3;
        int inc = tsum;
        #pragma unroll
        for (int d = 1; d < 32; d <<= 1) {
            int v = __shfl_up_sync(0xffffffffu, inc, d);
            if (lane >= d) inc += v;
        }
        if (lane == 31) aux[w] = inc;
        __syncthreads();
        if (t == 0) {
            int acc = 0;
            for (int k = 0; k < 16; k++) { int v = aux[k]; aux[k] = acc; acc += v; }
        }
        __syncthreads();
        int excl = aux[w] + (inc - tsum);
        off[base]     = excl;
        off[base + 1] = excl + h0;
        off[base + 2] = excl + h0 + h1;
        off[base + 3] = excl + h0 + h1 + h2;
        cnt[base] = excl; cnt[base+1] = excl + h0;
        cnt[base+2] = excl + h0 + h1; cnt[base+3] = excl + h0 + h1 + h2;
        if (t == 0) off[NBUCK] = Nq;
        __syncthreads();

        // scatter member list (order within bucket arbitrary; result invariant)
        for (int m = t; m < Nq; m += NTHR) {
            int bk = (int)((kb[m] - minv) * scale);
            bk = max(0, min(NBUCK - 1, bk));
            int slot = atomicAdd(&cnt[bk], 1);
            blist[slot] = m;
        }
        __syncthreads();

        // deterministic rank within bucket; write sorted keys + perm
        for (int m = t; m < Nq; m += NTHR) {
            float v = kb[m];
            int bk = (int)((v - minv) * scale);
            bk = max(0, min(NBUCK - 1, bk));
            int lo = off[bk], hi = off[bk + 1];
            int r = lo;
            for (int j = lo; j < hi; j++) {
                int jm = blist[j];
                float vj = kb[jm];
                r += (vj < v) || (vj == v && jm < m);
            }
            s_keys[b*Nq + r] = v;
            s_perm[b*Nq + r] = m;
        }
    }
    gsync();

    // ================= P3: chunk totals + per-position k* =================
    {
        float* keys_sm = (float*)SM;                  // 2304
        for (int item = blockIdx.x; item < 144; item += GRID) {
            int b = item / 18, sub = item % 18;
            for (int idx = t; idx < Nq; idx += NTHR)
                keys_sm[idx] = s_keys[b*Nq + idx];
            __syncthreads();

            int w = t >> 5, lane = t & 31;
            if (w < 4) {
                int chunk = sub*4 + w;
                int k0 = chunk * CHSZ;
                const float* gxb = s_gx + b*Nq*CIq;
                const int* permb = s_perm + b*Nq;
                float ag = 0.f, abg = 0.f;
                #pragma unroll
                for (int k = k0; k < k0 + CHSZ; k++) {
                    int m = permb[k];
                    float gg = gxb[m*CIq + lane];
                    ag += gg;
                    abg = fmaf(keys_sm[k], gg, abg);
                }
                s_ctg [(b*NCH + chunk)*CIq + lane] = ag;
                s_ctbg[(b*NCH + chunk)*CIq + lane] = abg;
            } else if (w < 8) {
                int pos = sub*128 + (t - 128);
                float thr = -s_a[b*Nq + pos];
                int lo = 0, hi = Nq;
                while (lo < hi) {
                    int mid = (lo + hi) >> 1;
                    if (keys_sm[mid] <= thr) lo = mid + 1; else hi = mid;
                }
                s_kstar[b*Nq + pos] = lo;
            }
            __syncthreads();
        }
    }
    gsync();

    // ================= P4: suffix sums (2 warps per chunk) =================
    {
        int w16 = t >> 5, lane = t & 31;
        for (int item = blockIdx.x; item < 72; item += GRID) {
            int b = item / 9, cb = item % 9;
            int chunk = cb*8 + (w16 >> 1), hc = w16 & 1;
            float rg = 0.f, rbg = 0.f;
            #pragma unroll 4
            for (int ch = chunk + 1; ch < NCH; ch++) {
                rg  += s_ctg [(b*NCH + ch)*CIq + lane];
                rbg += s_ctbg[(b*NCH + ch)*CIq + lane];
            }
            const float* gxb = s_gx + b*Nq*CIq;
            const int* permb = s_perm + b*Nq;
            const float* keyb = s_keys + b*Nq;
            int k0 = chunk * CHSZ;
            int   mlane = permb[k0 + lane];
            float klane = keyb[k0 + lane];
            if (hc == 0) {
                #pragma unroll
                for (int j = 31; j >= 16; j--) {
                    int   mm = __shfl_sync(0xffffffffu, mlane, j);
                    float kk = __shfl_sync(0xffffffffu, klane, j);
                    float gg = gxb[mm*CIq + lane];
                    rg += gg;
                    rbg = fmaf(kk, gg, rbg);
                }
            }
            int jstart = hc ? 16 : 0;
            float ag = rg, abg = rbg;
            #pragma unroll
            for (int j = jstart + 15; j >= jstart; j--) {
                int   mm = __shfl_sync(0xffffffffu, mlane, j);
                float kk = __shfl_sync(0xffffffffu, klane, j);
                float gg = gxb[mm*CIq + lane];
                ag += gg;
                abg = fmaf(kk, gg, abg);
                s_Sg [(b*NP1 + k0 + j)*CIq + lane] = ag;
                s_Sbg[(b*NP1 + k0 + j)*CIq + lane] = abg;
            }
            if (cb == 0 && w16 == 0) {
                s_Sg [(b*NP1 + Nq)*CIq + lane] = 0.f;
                s_Sbg[(b*NP1 + Nq)*CIq + lane] = 0.f;
            }
        }
    }
    gsync();

    // ================= P5: y lookup + W projection + BN partials =================
    {
        float* ws   = (float*)SM;                     // 64*33
        float* ys   = (float*)(SM + 8448);            // [2][64*36]
        float* a_sm = (float*)(SM + 26880);           // [2][64]
        int*   k_sm = (int*)(SM + 27392);             // [2][64]
        float* psum = (float*)(SM + 27904);           // [2][4*64]
        float* psq  = (float*)(SM + 29952);           // [2][4*64]

        for (int idx = t; idx < Cq*CIq; idx += NTHR)
            ws[(idx >> 5)*33 + (idx & 31)] = W_w[idx];
        __syncthreads();

        int half = t >> 8, tt = t & 255;
        float* ysh = ys + half*(64*36);
        int c = tt & 63, sub = tt >> 6;
        float wreg[CIq];
        #pragma unroll
        for (int i = 0; i < CIq; i++) wreg[i] = ws[c*33 + i];
        float wbc = W_b[c];

        for (int pair = blockIdx.x; pair < NTILE/2; pair += GRID) {
            int tile = pair*2 + half;
            int b = tile / TILES, n0 = (tile % TILES)*64;
            if (tt < 64) {
                a_sm[half*64 + tt] = s_a[b*Nq + n0 + tt];
                k_sm[half*64 + tt] = s_kstar[b*Nq + n0 + tt];
            }
            __syncthreads();

            {
                int i = tt & 31, pg = tt >> 5;
                #pragma unroll
                for (int p = 0; p < 8; p++) {
                    int pos = pg*8 + p;
                    int k = k_sm[half*64 + pos];
                    float sg  = s_Sg [(b*NP1 + k)*CIq + i];
                    float sbg = s_Sbg[(b*NP1 + k)*CIq + i];
                    ysh[pos*36 + i] = fmaf(a_sm[half*64 + pos], sg, sbg) * (1.0f / (float)Nq);
                }
            }
            __syncthreads();

            {
                float ls = 0.f, ls2 = 0.f;
                float* wyrow = s_wy + (b*Cq + c)*Nq + n0 + sub*16;
                #pragma unroll
                for (int q4 = 0; q4 < 4; q4++) {
                    float av[4];
                    #pragma unroll
                    for (int u = 0; u < 4; u++) {
                        int pos = sub*16 + q4*4 + u;
                        const float4* yv = (const float4*)&ysh[pos*36];
                        float acc = 0.f;
                        #pragma unroll
                        for (int i4 = 0; i4 < CIq/4; i4++) {
                            float4 v = yv[i4];
                            acc = fmaf(wreg[i4*4+0], v.x, acc);
                            acc = fmaf(wreg[i4*4+1], v.y, acc);
                            acc = fmaf(wreg[i4*4+2], v.z, acc);
                            acc = fmaf(wreg[i4*4+3], v.w, acc);
                        }
                        av[u] = acc;
                        ls += acc; ls2 = fmaf(acc, acc, ls2);
                    }
                    float4 o;
                    o.x = av[0] + wbc; o.y = av[1] + wbc;
                    o.z = av[2] + wbc; o.w = av[3] + wbc;
                    *(float4*)(wyrow + q4*4) = o;
                }
                psum[half*256 + sub*64 + c] = ls;
                psq [half*256 + sub*64 + c] = ls2;
            }
            __syncthreads();

            if (tt < 64) {
                int o = half*256;
                float s  = psum[o+tt] + psum[o+64+tt] + psum[o+128+tt] + psum[o+192+tt];
                float s2 = psq[o+tt]  + psq[o+64+tt]  + psq[o+128+tt]  + psq[o+192+tt];
                s_part[(tile*Cq + tt)*2 + 0] = s;
                s_part[(tile*Cq + tt)*2 + 1] = s2;
            }
            __syncthreads();
        }
    }
    gsync();

    // ================= P6: BN stats (redundant per block) + final =================
    {
        float* red   = (float*)SM;            // [8][64] sums + [8][64] sumsq
        float* scale = (float*)(SM + 4096);   // 64
        float* shift = (float*)(SM + 4352);   // 64

        int c = t & 63, r = t >> 6;           // r: 0..7
        float s = 0.f, s2 = 0.f;
        const float2* pp = (const float2*)s_part;
        for (int blk = r; blk < NTILE; blk += 8) {
            float2 v = pp[blk*Cq + c];
            s += v.x; s2 += v.y;
        }
        red[r*64 + c] = s;
        red[512 + r*64 + c] = s2;
        __syncthreads();
        if (t < 64) {
            float ss = 0.f, qq = 0.f;
            #pragma unroll
            for (int rr = 0; rr < 8; rr++) {
                ss += red[rr*64 + t];
                qq += red[512 + rr*64 + t];
            }
            const float M = (float)(Bq * Nq);
            float mv = ss / M;
            float var = qq / M - mv*mv;
            float mean = W_b[t] + mv;
            float sc = bn_g[t] * rsqrtf(var + 1e-5f);
            scale[t] = sc;
            shift[t] = bn_b[t] - mean*sc;
        }
        __syncthreads();

        const int TOT4 = Bq*Cq*Nq/4;
        const float4* wy4 = (const float4*)s_wy;
        const float4* x4  = (const float4*)x;
        float4* o4 = (float4*)out;
        for (int i4 = blockIdx.x*NTHR + t; i4 < TOT4; i4 += GRID*NTHR) {
            int c2 = (i4 / (Nq/4)) & 63;
            float sc = scale[c2], sh = shift[c2];
            float4 w = wy4[i4];
            float4 xv = x4[i4];
            float4 o;
            o.x = fmaf(w.x, sc, sh) + xv.x;
            o.y = fmaf(w.y, sc, sh) + xv.y;
            o.z = fmaf(w.z, sc, sh) + xv.z;
            o.w = fmaf(w.w, sc, sh) + xv.w;
            o4[i4] = o;
        }
    }
}

// ---------------- launch ----------------
extern "C" void kernel_launch(void* const* d_in, const int* in_sizes, int n_in,
                              void* d_out, int out_size) {
    const float* x     = (const float*)d_in[0];
    const float* g_w   = (const float*)d_in[1];
    const float* g_b   = (const float*)d_in[2];
    const float* th_w  = (const float*)d_in[3];
    const float* th_b  = (const float*)d_in[4];
    const float* ph_w  = (const float*)d_in[5];
    const float* ph_b  = (const float*)d_in[6];
    const float* cp_wt = (const float*)d_in[7];
    const float* cp_wp = (const float*)d_in[8];
    const float* W_w   = (const float*)d_in[9];
    const float* W_b   = (const float*)d_in[10];
    const float* bn_g  = (const float*)d_in[11];
    const float* bn_b  = (const float*)d_in[12];
    float* out = (float*)d_out;

    fused_nonlocal<<<GRID, NTHR>>>(x, g_w, g_b, th_w, th_b, ph_w, ph_b,
                                   cp_wt, cp_wp, W_w, W_b, bn_g, bn_b, out);
}